// round 5
// baseline (speedup 1.0000x reference)
#include <cuda_runtime.h>
#include <cuda_bf16.h>
#include <cstdint>

// Problem constants (fixed by the reference)
#define N_COLS  22
#define N_PAIRS 231
#define EMB     12
#define DVEC    64
#define N_PRIM  5
#define COMBO2  (EMB * EMB * 2)   // 288 floats per pair in the LUT
#define NCHUNK  4                 // pair-dimension split for kernel 2
#define CHUNKSZ ((N_PAIRS + NCHUNK - 1) / NCHUNK)   // 58

// Scratch: precomputed per-pair lookup table T[p][fi][fj][o]  (266 KB)
__device__ __align__(16) float g_T[N_PAIRS * COMBO2];

// ---------------------------------------------------------------------------
// Kernel 1: build T[p, fi, fj, o] = sum_d w_sel[p,o,d] * op_sel(ti[fi,d], tj[fj,d])
// One block per pair; 288 threads, one per (fi, fj, o) task. float4 inner loop.
// Also zero-initializes out[] (grid-stride) so kernel 2 can atomicAdd.
// ---------------------------------------------------------------------------
#define ROWSTRIDE (DVEC + 4)      // 68 floats: keeps float4 alignment, shifts banks by 4/row

__global__ __launch_bounds__(COMBO2)
void build_lut_kernel(const float* __restrict__ tables,
                      const float* __restrict__ Wsmall,
                      const float* __restrict__ Wconcat,
                      const float* __restrict__ aw,
                      float* __restrict__ out, int outN)
{
    const int p = blockIdx.x;

    // zero the output buffer (poisoned by harness); same-stream ordering makes
    // this visible to kernel 2's atomics
    for (int e = blockIdx.x * COMBO2 + threadIdx.x; e < outN; e += gridDim.x * COMBO2)
        out[e] = 0.0f;

    // pair p -> (i, j) of triu(N_COLS, k=1), row-major order
    int i = 0, r = p, c = N_COLS - 1;
    while (r >= c) { r -= c; ++i; --c; }
    const int j = i + 1 + r;

    // selected primitive (arch_weights is exact one-hot of 0.0 / 1.0)
    int k = 0;
#pragma unroll
    for (int t = 0; t < N_PRIM; ++t)
        if (aw[p * N_PRIM + t] > 0.5f) k = t;

    // stage the 12 candidate embedding vectors for columns i and j
    __shared__ float shi[EMB * ROWSTRIDE];
    __shared__ float shj[EMB * ROWSTRIDE];
    for (int e = threadIdx.x; e < EMB * DVEC; e += blockDim.x) {
        const int row = e >> 6, d = e & 63;
        shi[row * ROWSTRIDE + d] = tables[(i * EMB + row) * DVEC + d];
        shj[row * ROWSTRIDE + d] = tables[(j * EMB + row) * DVEC + d];
    }
    __syncthreads();

    const int task  = threadIdx.x;          // 0..287
    const int o     = task & 1;
    const int combo = task >> 1;            // fi*12 + fj
    const int fi    = combo / EMB;
    const int fj    = combo - fi * EMB;

    const float4* __restrict__ pi = (const float4*)&shi[fi * ROWSTRIDE];
    const float4* __restrict__ pj = (const float4*)&shj[fj * ROWSTRIDE];

    float acc = 0.0f;
    if (k == 4) {
        const float4* __restrict__ wa = (const float4*)(Wconcat + (p * 2 + o) * (2 * DVEC));
        const float4* __restrict__ wb = wa + (DVEC / 4);
#pragma unroll
        for (int d = 0; d < DVEC / 4; ++d) {
            const float4 a = pi[d], b = pj[d];
            const float4 u = __ldg(&wa[d]), v = __ldg(&wb[d]);
            acc += u.x * a.x + u.y * a.y + u.z * a.z + u.w * a.w;
            acc += v.x * b.x + v.y * b.y + v.z * b.z + v.w * b.w;
        }
    } else {
        const float4* __restrict__ w = (const float4*)(Wsmall + ((p * 4 + k) * 2 + o) * DVEC);
#pragma unroll
        for (int d = 0; d < DVEC / 4; ++d) {
            const float4 a = pi[d], b = pj[d];
            const float4 u = __ldg(&w[d]);
            float4 z;
            if (k == 0)      { z.x = a.x + b.x; z.y = a.y + b.y; z.z = a.z + b.z; z.w = a.w + b.w; }
            else if (k == 1) { z.x = a.x * b.x; z.y = a.y * b.y; z.z = a.z * b.z; z.w = a.w * b.w; }
            else if (k == 2) { z.x = fmaxf(a.x, b.x); z.y = fmaxf(a.y, b.y); z.z = fmaxf(a.z, b.z); z.w = fmaxf(a.w, b.w); }
            else             { z.x = fminf(a.x, b.x); z.y = fminf(a.y, b.y); z.z = fminf(a.z, b.z); z.w = fminf(a.w, b.w); }
            acc += u.x * z.x + u.y * z.y + u.z * z.z + u.w * z.w;
        }
    }
    g_T[p * COMBO2 + combo * 2 + o] = acc;
}

// ---------------------------------------------------------------------------
// Kernel 2: out[b, :] += sum_{p in chunk} T[p, f[i_p], f[j_p], :]
// grid = (B/32) x NCHUNK. lane = batch element (32/block); warp w of 8 strides
// its chunk's ~58 pairs (7-8 independent gathers, unrolled -> full MLP).
// All 32 lanes of a warp gather inside ONE pair's 1.15 KB LUT region
// (L1-coherent, ~10 lines per load). Cross-warp SMEM reduce, then one
// atomicAdd per output scalar per chunk (out zeroed by kernel 1).
// ---------------------------------------------------------------------------
__global__ __launch_bounds__(256)
void accumulate_kernel(const int* __restrict__ feats,
                       float* __restrict__ out,
                       int B)
{
    __shared__ int    shf[32][N_COLS + 1];   // stride 23: coprime with 32 banks
    __shared__ uchar2 shp[CHUNKSZ];
    __shared__ float2 shred[8][32];

    const int tid   = threadIdx.x;
    const int lane  = tid & 31;
    const int warp  = tid >> 5;
    const int bbase = blockIdx.x * 32;
    const int p0    = blockIdx.y * CHUNKSZ;
    const int p1    = min(N_PAIRS, p0 + CHUNKSZ);
    const int npair = p1 - p0;

    // coalesced, cooperative load of this block's 32 feats rows
    for (int e = tid; e < 32 * N_COLS; e += 256) {
        const int row = e / N_COLS, col = e - row * N_COLS;
        const int b   = bbase + row;
        shf[row][col] = (b < B) ? feats[b * N_COLS + col] : 0;
    }
    // (i, j) byte table for this chunk's pairs
    for (int t = tid; t < npair; t += 256) {
        const int p = p0 + t;
        int i = 0, r = p, c = N_COLS - 1;
        while (r >= c) { r -= c; ++i; --c; }
        shp[t] = make_uchar2((unsigned char)i, (unsigned char)(i + 1 + r));
    }
    __syncthreads();

    const float2* __restrict__ T2 = (const float2*)g_T;
    float ax = 0.0f, ay = 0.0f;

    // warp w handles chunk-local pairs w, w+8, ... (<= 8 independent gathers)
#pragma unroll 8
    for (int t = warp; t < npair; t += 8) {
        const uchar2 ij = shp[t];
        const int fi = shf[lane][ij.x];
        const int fj = shf[lane][ij.y];
        const float2 v = __ldg(&T2[(p0 + t) * (EMB * EMB) + fi * EMB + fj]);
        ax += v.x;
        ay += v.y;
    }

    shred[warp][lane] = make_float2(ax, ay);
    __syncthreads();

    if (warp == 0) {
        float sx = 0.0f, sy = 0.0f;
#pragma unroll
        for (int w = 0; w < 8; ++w) {
            const float2 s = shred[w][lane];
            sx += s.x;
            sy += s.y;
        }
        const int b = bbase + lane;
        if (b < B) {
            atomicAdd(&out[b * 2 + 0], sx);
            atomicAdd(&out[b * 2 + 1], sy);
        }
    }
}

// ---------------------------------------------------------------------------
// Launch: two kernels on the default stream (implicit ordering), graph-safe.
// Inputs (metadata order): feats(i32), tables(f32), W_small(f32),
//                          W_concat(f32), arch_weights(f32)
// ---------------------------------------------------------------------------
extern "C" void kernel_launch(void* const* d_in, const int* in_sizes, int n_in,
                              void* d_out, int out_size)
{
    const int*   feats   = (const int*)  d_in[0];
    const float* tables  = (const float*)d_in[1];
    const float* Wsmall  = (const float*)d_in[2];
    const float* Wconcat = (const float*)d_in[3];
    const float* aw      = (const float*)d_in[4];
    float*       out     = (float*)d_out;

    const int B = in_sizes[0] / N_COLS;   // 4096

    build_lut_kernel<<<N_PAIRS, COMBO2>>>(tables, Wsmall, Wconcat, aw, out, out_size);

    dim3 grid((B + 31) / 32, NCHUNK);     // 128 x 4 = 512 blocks
    accumulate_kernel<<<grid, 256>>>(feats, out, B);
}